// round 6
// baseline (speedup 1.0000x reference)
#include <cuda_runtime.h>
#include <cstdint>

// Problem constants
constexpr int B_  = 256;
constexpr int T_  = 512;
constexpr int H_  = 256;
constexpr int KA  = 384;   // augmented K: 256 (h) + 128 (x)

// Scan decomposition: 16 clusters of 8 CTAs; CTA owns 32 columns, 16 batch rows.
constexpr int NC  = 8;
constexpr int HC  = 32;
constexpr int NBG = 16;
constexpr int NB  = 16;

// ---------------- device scratch ----------------
__device__ float g_h [NBG][NB][H_];          // pre-decayed h exchange (via L2)
__device__ float g_rh[NBG][NB][H_];          // (r * h_dec) exchange

// ---------------- f32x2 helpers ----------------
__device__ __forceinline__ unsigned long long pack2(float a, float b) {
    unsigned long long r;
    asm("mov.b64 %0, {%1,%2};" : "=l"(r) : "f"(a), "f"(b));
    return r;
}
__device__ __forceinline__ void fma2(unsigned long long& d, unsigned long long a, unsigned long long b) {
    asm("fma.rn.f32x2 %0, %1, %2, %0;" : "+l"(d) : "l"(a), "l"(b));
}
__device__ __forceinline__ unsigned long long add2(unsigned long long a, unsigned long long b) {
    unsigned long long r;
    asm("add.rn.f32x2 %0, %1, %2;" : "=l"(r) : "l"(a), "l"(b));
    return r;
}
__device__ __forceinline__ float fold2(unsigned long long v) {
    float lo, hi;
    asm("mov.b64 {%0,%1}, %2;" : "=f"(lo), "=f"(hi) : "l"(v));
    return lo + hi;
}

__device__ __forceinline__ float sigmoid_(float v) {
    float e = __expf(-v);
    return __fdividef(1.f, 1.f + e);
}
__device__ __forceinline__ float tanh_(float v) {
    float e = __expf(2.f * v);
    return __fdividef(e - 1.f, e + 1.f);
}

// ---------------- cluster mbarrier primitives ----------------
__device__ __forceinline__ void mbar_init(uint32_t addr, uint32_t count) {
    asm volatile("mbarrier.init.shared.b64 [%0], %1;" :: "r"(addr), "r"(count) : "memory");
}
// Arrive at peer `rank`'s mbarrier (release at cluster scope: prior global
// stores become visible to threads that acquire this barrier).
__device__ __forceinline__ void mbar_remote_arrive(uint32_t local_addr, uint32_t rank) {
    asm volatile(
        "{\n\t"
        ".reg .b32 ra;\n\t"
        "mapa.shared::cluster.u32 ra, %0, %1;\n\t"
        "mbarrier.arrive.release.cluster.shared::cluster.b64 _, [ra];\n\t"
        "}"
        :: "r"(local_addr), "r"(rank) : "memory");
}
__device__ __forceinline__ void mbar_wait_parity(uint32_t addr, uint32_t parity) {
    asm volatile(
        "{\n\t"
        ".reg .pred P;\n\t"
        "WAIT_%=:\n\t"
        "mbarrier.try_wait.parity.acquire.cluster.shared::cta.b64 P, [%0], %1, 10000000;\n\t"
        "@P bra.uni DONE_%=;\n\t"
        "bra.uni WAIT_%=;\n\t"
        "DONE_%=:\n\t"
        "}"
        :: "r"(addr), "r"(parity) : "memory");
}

// ================= fused persistent recurrent scan =================
// Augmented GEMM: pre-activation = [h_dec | x_t] @ [U ; W] + b for each gate.
// Weights (384 x 32 per gate) live in registers, k split across 8 warps (48 k each).
__global__ void __cluster_dims__(NC, 1, 1) __launch_bounds__(256, 1)
scan_kernel(
    const float* __restrict__ x,
    const float* __restrict__ Uz, const float* __restrict__ Ur, const float* __restrict__ Uh,
    const float* __restrict__ Wz, const float* __restrict__ Wr, const float* __restrict__ Wh,
    const float* __restrict__ bz, const float* __restrict__ br, const float* __restrict__ bh,
    const float* __restrict__ hdecay, float* __restrict__ out)
{
    extern __shared__ float sm[];
    float* asm_s = sm;                                              // [16][384]  24KB
    unsigned long long* red_z = (unsigned long long*)(sm + 6144);   // [8][16][32] 32KB
    unsigned long long* red_r = (unsigned long long*)(sm + 14336);  // [8][16][32] 32KB

    __shared__ __align__(8) unsigned long long s_barA, s_barB;

    const int tid = threadIdx.x;
    const int w = tid >> 5;          // warp -> k block [48w, 48w+48)
    const int l = tid & 31;          // lane -> local column
    const int grp = blockIdx.x >> 3;
    const int cg  = blockIdx.x & 7;  // == cluster rank
    const int j = cg * HC + l;       // global column
    const int b0g = grp * NB;

    const uint32_t barA = (uint32_t)__cvta_generic_to_shared(&s_barA);
    const uint32_t barB = (uint32_t)__cvta_generic_to_shared(&s_barB);

    if (tid == 0) { mbar_init(barA, NC); mbar_init(barB, NC); }
    // make peers' mbarrier init visible before any remote arrive
    asm volatile("barrier.cluster.arrive.aligned;" ::: "memory");
    asm volatile("barrier.cluster.wait.aligned;"   ::: "memory");

    // --- augmented weight slices into registers (packed f32x2 over k-pairs) ---
    unsigned long long uz2[24], ur2[24], uh2[24];
    #pragma unroll
    for (int p = 0; p < 24; ++p) {
        int k = w * 48 + 2 * p;
        float z0, z1, r0, r1, h0, h1;
        if (k < 256) {
            z0 = Uz[(size_t)k * H_ + j]; z1 = Uz[(size_t)(k + 1) * H_ + j];
            r0 = Ur[(size_t)k * H_ + j]; r1 = Ur[(size_t)(k + 1) * H_ + j];
            h0 = Uh[(size_t)k * H_ + j]; h1 = Uh[(size_t)(k + 1) * H_ + j];
        } else {
            int kk = k - 256;
            z0 = Wz[(size_t)kk * H_ + j]; z1 = Wz[(size_t)(kk + 1) * H_ + j];
            r0 = Wr[(size_t)kk * H_ + j]; r1 = Wr[(size_t)(kk + 1) * H_ + j];
            h0 = Wh[(size_t)kk * H_ + j]; h1 = Wh[(size_t)(kk + 1) * H_ + j];
        }
        uz2[p] = pack2(z0, z1);
        ur2[p] = pack2(r0, r1);
        uh2[p] = pack2(h0, h1);
    }
    const float bzv = bz[j], brv = br[j], bhv = bh[j];

    // x staging mapping: thread -> (row = tid>>4, 8 floats at seg*8)
    const int xrow = tid >> 4;
    const int xseg = tid & 15;

    // --- t=0: h_dec = 0; stage x(0) ---
    #pragma unroll
    for (int i = 0; i < 16; ++i) asm_s[(tid >> 4) * 384 + (tid & 15) * 16 + (i)] = 0.f;
    // (covers [row][0..256): 16 threads/row x 16 floats each)
    {
        const float* xr_ = &x[((size_t)(b0g + xrow) * T_ + 0) * 128 + xseg * 8];
        float4 a = *(const float4*)xr_;
        float4 b = *(const float4*)(xr_ + 4);
        *(float4*)&asm_s[xrow * 384 + 256 + xseg * 8] = a;
        *(float4*)&asm_s[xrow * 384 + 256 + xseg * 8 + 4] = b;
    }
    __syncthreads();

    for (int t = 0; t < T_; ++t) {
        const uint32_t parity = (uint32_t)(t & 1);
        const size_t m0 = (size_t)(b0g + w) * T_ + t;
        const size_t m1 = (size_t)(b0g + w + 8) * T_ + t;
        const bool more = (t + 1 < T_);

        float decn0 = 0.f, decn1 = 0.f;
        if (more) { decn0 = hdecay[m0 + 1]; decn1 = hdecay[m1 + 1]; }
        const float hd0 = asm_s[w * 384 + j];
        const float hd1 = asm_s[(w + 8) * 384 + j];

        // ---- merged z+r augmented GEMM (one pass over asm_s rows) ----
        #pragma unroll 1
        for (int b = 0; b < NB; ++b) {
            unsigned long long az0 = 0, az1 = 0, ar0 = 0, ar1 = 0;
            const float* hrow = &asm_s[b * 384 + w * 48];
            #pragma unroll
            for (int q = 0; q < 12; ++q) {
                ulonglong2 hv = *(const ulonglong2*)(hrow + q * 4);
                fma2(az0, hv.x, uz2[2 * q]);
                fma2(az1, hv.y, uz2[2 * q + 1]);
                fma2(ar0, hv.x, ur2[2 * q]);
                fma2(ar1, hv.y, ur2[2 * q + 1]);
            }
            red_z[(w * 16 + b) * 32 + l] = add2(az0, az1);
            red_r[(w * 16 + b) * 32 + l] = add2(ar0, ar1);
        }
        __syncthreads();

        // ---- r reduce + publish rh ----
        {
            unsigned long long s0 = 0, s1 = 0;
            #pragma unroll
            for (int ww = 0; ww < 8; ++ww) {
                s0 = add2(s0, red_r[(ww * 16 + w) * 32 + l]);
                s1 = add2(s1, red_r[(ww * 16 + w + 8) * 32 + l]);
            }
            float r0 = sigmoid_(fold2(s0) + brv);
            float r1 = sigmoid_(fold2(s1) + brv);
            __stcg(&g_rh[grp][w][j],     r0 * hd0);
            __stcg(&g_rh[grp][w + 8][j], r1 * hd1);
        }
        __syncthreads();                 // all rh stores issued
        if (tid < NC) mbar_remote_arrive(barA, (uint32_t)tid);

        // ---- z reduce (fills barrier-A propagation) ----
        float zv0, zv1;
        {
            unsigned long long s0 = 0, s1 = 0;
            #pragma unroll
            for (int ww = 0; ww < 8; ++ww) {
                s0 = add2(s0, red_z[(ww * 16 + w) * 32 + l]);
                s1 = add2(s1, red_z[(ww * 16 + w + 8) * 32 + l]);
            }
            zv0 = sigmoid_(fold2(s0) + bzv);
            zv1 = sigmoid_(fold2(s1) + bzv);
        }
        mbar_wait_parity(barA, parity);

        // ---- gather full rh rows into asm_s[.][0..256) ----
        #pragma unroll
        for (int it = 0; it < 4; ++it) {
            int idx = tid + it * 256;
            int b = idx >> 6, k4 = idx & 63;
            float4 v = __ldcg((const float4*)&g_rh[grp][b][k4 * 4]);
            *(float4*)&asm_s[b * 384 + k4 * 4] = v;
        }
        __syncthreads();

        // ---- h augmented GEMM ----
        #pragma unroll 1
        for (int b = 0; b < NB; ++b) {
            unsigned long long ah0 = 0, ah1 = 0;
            const float* hrow = &asm_s[b * 384 + w * 48];
            #pragma unroll
            for (int q = 0; q < 12; ++q) {
                ulonglong2 hv = *(const ulonglong2*)(hrow + q * 4);
                fma2(ah0, hv.x, uh2[2 * q]);
                fma2(ah1, hv.y, uh2[2 * q + 1]);
            }
            red_z[(w * 16 + b) * 32 + l] = add2(ah0, ah1);
        }
        __syncthreads();

        // ---- h reduce, combine, publish pre-decayed h ----
        float h0, h1;
        {
            unsigned long long s0 = 0, s1 = 0;
            #pragma unroll
            for (int ww = 0; ww < 8; ++ww) {
                s0 = add2(s0, red_z[(ww * 16 + w) * 32 + l]);
                s1 = add2(s1, red_z[(ww * 16 + w + 8) * 32 + l]);
            }
            float hp0 = tanh_(fold2(s0) + bhv);
            float hp1 = tanh_(fold2(s1) + bhv);
            h0 = (1.f - zv0) * hd0 + zv0 * hp0;
            h1 = (1.f - zv1) * hd1 + zv1 * hp1;
            if (more) {
                __stcg(&g_h[grp][w][j],     h0 * decn0);
                __stcg(&g_h[grp][w + 8][j], h1 * decn1);
            }
        }

        if (more) {
            __syncthreads();             // all g_h stores issued
            if (tid < NC) mbar_remote_arrive(barB, (uint32_t)tid);

            // off-critical-path: outputs + next x prefetch
            __stcg(&out[m0 * 256 + j], h0);
            __stcg(&out[m1 * 256 + j], h1);
            const float* xr_ = &x[((size_t)(b0g + xrow) * T_ + (t + 1)) * 128 + xseg * 8];
            float4 xa = *(const float4*)xr_;
            float4 xb = *(const float4*)(xr_ + 4);

            mbar_wait_parity(barB, parity);

            // ---- assemble next h_dec (pre-decayed) + stage next x ----
            #pragma unroll
            for (int it = 0; it < 4; ++it) {
                int idx = tid + it * 256;
                int b = idx >> 6, k4 = idx & 63;
                float4 v = __ldcg((const float4*)&g_h[grp][b][k4 * 4]);
                *(float4*)&asm_s[b * 384 + k4 * 4] = v;
            }
            *(float4*)&asm_s[xrow * 384 + 256 + xseg * 8]     = xa;
            *(float4*)&asm_s[xrow * 384 + 256 + xseg * 8 + 4] = xb;
            __syncthreads();
        } else {
            __stcg(&out[m0 * 256 + j], h0);
            __stcg(&out[m1 * 256 + j], h1);
        }
    }
}

// ================= launch =================
extern "C" void kernel_launch(void* const* d_in, const int* /*in_sizes*/, int /*n_in*/,
                              void* d_out, int /*out_size*/)
{
    const float* x      = (const float*)d_in[0];
    const float* hdecay = (const float*)d_in[1];
    const float* Wr = (const float*)d_in[2];
    const float* Wz = (const float*)d_in[3];
    const float* Wh = (const float*)d_in[4];
    const float* Ur = (const float*)d_in[5];
    const float* Uz = (const float*)d_in[6];
    const float* Uh = (const float*)d_in[7];
    const float* br = (const float*)d_in[8];
    const float* bz = (const float*)d_in[9];
    const float* bh = (const float*)d_in[10];
    float* out = (float*)d_out;

    constexpr int SMEM_SCAN = 22528 * 4;   // 88KB dynamic
    cudaFuncSetAttribute(scan_kernel, cudaFuncAttributeMaxDynamicSharedMemorySize, SMEM_SCAN);

    scan_kernel<<<NBG * NC, 256, SMEM_SCAN>>>(
        x, Uz, Ur, Uh, Wz, Wr, Wh, bz, br, bh, hdecay, out);
}

// round 7
// speedup vs baseline: 1.9083x; 1.9083x over previous
#include <cuda_runtime.h>
#include <cstdint>

// Problem constants
constexpr int B_  = 256;
constexpr int T_  = 512;
constexpr int H_  = 256;
constexpr int MTOT = B_ * T_;
constexpr size_t MH = (size_t)MTOT * H_;

// Scan decomposition: 16 batch groups x 8 column CTAs
constexpr int NC  = 8;
constexpr int HC  = 32;
constexpr int NBG = 16;
constexpr int NB  = 16;

// ---------------- device scratch ----------------
__device__ float g_xp[3 * MH];                 // projected inputs [gate][m][H]
__device__ float g_h [2][NBG][NB][H_];         // pre-decayed h, double-buffered
__device__ float g_rh[2][NBG][NB][H_];         // r*h_dec, double-buffered
__device__ unsigned g_rdy_rh[NBG][NC][32];     // per-producer flags (128B padded)
__device__ unsigned g_rdy_h [NBG][NC][32];

// ---------------- f32x2 helpers ----------------
__device__ __forceinline__ unsigned long long pack2(float a, float b) {
    unsigned long long r;
    asm("mov.b64 %0, {%1,%2};" : "=l"(r) : "f"(a), "f"(b));
    return r;
}
__device__ __forceinline__ void fma2(unsigned long long& d, unsigned long long a, unsigned long long b) {
    asm("fma.rn.f32x2 %0, %1, %2, %0;" : "+l"(d) : "l"(a), "l"(b));
}
__device__ __forceinline__ unsigned long long add2(unsigned long long a, unsigned long long b) {
    unsigned long long r;
    asm("add.rn.f32x2 %0, %1, %2;" : "=l"(r) : "l"(a), "l"(b));
    return r;
}
__device__ __forceinline__ float fold2(unsigned long long v) {
    float lo, hi;
    asm("mov.b64 {%0,%1}, %2;" : "=f"(lo), "=f"(hi) : "l"(v));
    return lo + hi;
}

__device__ __forceinline__ float sigmoid_(float v) {
    float e = __expf(-v);
    return __fdividef(1.f, 1.f + e);
}
__device__ __forceinline__ float tanh_(float v) {
    float e = __expf(2.f * v);
    return __fdividef(e - 1.f, e + 1.f);
}

// ---------------- flag primitives (producer/consumer, gpu scope) ----------------
__device__ __forceinline__ void set_flag(unsigned* f, unsigned v) {
    asm volatile("st.release.gpu.global.u32 [%0], %1;" :: "l"(f), "r"(v) : "memory");
}
__device__ __forceinline__ void poll_ge(const unsigned* f, unsigned need) {
    unsigned v;
    do {
        asm volatile("ld.acquire.gpu.global.u32 %0, [%1];" : "=r"(v) : "l"(f) : "memory");
    } while (v < need);
}

// ================= projection GEMM (R2 scalar version, measured 571us) =================
__global__ __launch_bounds__(256) void proj_kernel(
    const float* __restrict__ x,
    const float* __restrict__ Wz, const float* __restrict__ Wr, const float* __restrict__ Wh,
    const float* __restrict__ bz, const float* __restrict__ br, const float* __restrict__ bh)
{
    __shared__ float As[32 * 132];
    __shared__ float Bs[32 * 64];

    const int g = blockIdx.z;
    const float* W    = (g == 0) ? Wz : (g == 1) ? Wr : Wh;
    const float* bias = (g == 0) ? bz : (g == 1) ? br : bh;
    float* out = g_xp + (size_t)g * MH;

    const int mtile = blockIdx.x * 128;
    const int ntile = blockIdx.y * 64;
    const int tid = threadIdx.x;
    const int tm = tid >> 4;
    const int tn = tid & 15;

    float acc[8][4] = {};

    for (int kc = 0; kc < 128; kc += 32) {
        __syncthreads();
        #pragma unroll
        for (int it = 0; it < 4; ++it) {
            int idx = tid + it * 256;
            int m = idx >> 3, c4 = idx & 7;
            float4 v = *(const float4*)&x[(size_t)(mtile + m) * 128 + kc + c4 * 4];
            As[(c4 * 4 + 0) * 132 + m] = v.x;
            As[(c4 * 4 + 1) * 132 + m] = v.y;
            As[(c4 * 4 + 2) * 132 + m] = v.z;
            As[(c4 * 4 + 3) * 132 + m] = v.w;
        }
        #pragma unroll
        for (int it = 0; it < 2; ++it) {
            int idx = tid + it * 256;
            int kk = idx >> 4, n4 = idx & 15;
            float4 v = *(const float4*)&W[(size_t)(kc + kk) * 256 + ntile + n4 * 4];
            *(float4*)&Bs[kk * 64 + n4 * 4] = v;
        }
        __syncthreads();

        #pragma unroll
        for (int kk = 0; kk < 32; ++kk) {
            float4 a0 = *(const float4*)&As[kk * 132 + tm * 8];
            float4 a1 = *(const float4*)&As[kk * 132 + tm * 8 + 4];
            float4 bv = *(const float4*)&Bs[kk * 64 + tn * 4];
            float a[8] = {a0.x, a0.y, a0.z, a0.w, a1.x, a1.y, a1.z, a1.w};
            #pragma unroll
            for (int i = 0; i < 8; i++) {
                acc[i][0] += a[i] * bv.x;
                acc[i][1] += a[i] * bv.y;
                acc[i][2] += a[i] * bv.z;
                acc[i][3] += a[i] * bv.w;
            }
        }
    }

    float4 bb = *(const float4*)&bias[ntile + tn * 4];
    #pragma unroll
    for (int i = 0; i < 8; i++) {
        float4 o = make_float4(acc[i][0] + bb.x, acc[i][1] + bb.y,
                               acc[i][2] + bb.z, acc[i][3] + bb.w);
        *(float4*)&out[(size_t)(mtile + tm * 8 + i) * 256 + ntile + tn * 4] = o;
    }
}

// ================= reset: zero flags + g_h buffer 0 =================
__global__ void reset_kernel() {
    int i = blockIdx.x * 256 + threadIdx.x;
    if (i < NBG * NB * H_) ((float*)g_h)[i] = 0.f;                 // g_h[0] = 0
    if (i < NBG * NC * 32) {
        ((unsigned*)g_rdy_rh)[i] = 0;
        ((unsigned*)g_rdy_h)[i]  = 0;
    }
}

// ================= persistent recurrent scan (flag-pipelined) =================
// CTA (grp, cg) owns columns [32cg, 32cg+32). Warp w consumes ONLY CTA w's
// published slice; per-warp acquire flags replace group barriers.
__global__ __launch_bounds__(256, 1) void scan_kernel(
    const float* __restrict__ Uz, const float* __restrict__ Ur, const float* __restrict__ Uh,
    const float* __restrict__ hdecay, float* __restrict__ out)
{
    extern __shared__ float sm[];
    float* asm_h  = sm;                                             // [16][256] 16KB
    float* asm_rh = sm + 4096;                                      // [16][256] 16KB
    unsigned long long* red_z = (unsigned long long*)(sm + 8192);   // [8][16][32] 32KB
    unsigned long long* red_r = (unsigned long long*)(sm + 16384);  // [8][16][32] 32KB

    const int tid = threadIdx.x;
    const int w = tid >> 5;          // warp -> k block [32w, 32w+32), source CTA w
    const int l = tid & 31;
    const int grp = blockIdx.x >> 3;
    const int cg  = blockIdx.x & 7;
    const int j = cg * HC + l;
    const int b0g = grp * NB;

    // weights: packed f32x2 over k-pairs
    unsigned long long uz2[16], ur2[16], uh2[16];
    #pragma unroll
    for (int p = 0; p < 16; ++p) {
        int k = w * 32 + 2 * p;
        uz2[p] = pack2(Uz[(size_t)k * H_ + j], Uz[(size_t)(k + 1) * H_ + j]);
        ur2[p] = pack2(Ur[(size_t)k * H_ + j], Ur[(size_t)(k + 1) * H_ + j]);
        uh2[p] = pack2(Uh[(size_t)k * H_ + j], Uh[(size_t)(k + 1) * H_ + j]);
    }

    // flag addresses: poll source-CTA w's flags; publish own (cg)
    const unsigned* frh = &g_rdy_rh[grp][w][0];
    const unsigned* fh  = &g_rdy_h [grp][w][0];
    unsigned* myfrh = &g_rdy_rh[grp][cg][0];
    unsigned* myfh  = &g_rdy_h [grp][cg][0];

    // warp-local gather mapping: lane l -> row gr, float4 cols gh..gh+3
    const int gr = l >> 1;
    const int gh = (l & 1) * 4;

    // prefetch x projections for t=0
    size_t mb0 = (size_t)(b0g + w) * T_;
    size_t mb1 = (size_t)(b0g + w + 8) * T_;
    float xz0 = g_xp[mb0 * 256 + j],          xz1 = g_xp[mb1 * 256 + j];
    float xr0 = g_xp[MH + mb0 * 256 + j],     xr1 = g_xp[MH + mb1 * 256 + j];
    float xh0 = g_xp[2 * MH + mb0 * 256 + j], xh1 = g_xp[2 * MH + mb1 * 256 + j];

    for (int t = 0; t < T_; ++t) {
        const int p = t & 1;
        const size_t m0 = (size_t)(b0g + w) * T_ + t;
        const size_t m1 = (size_t)(b0g + w + 8) * T_ + t;
        const bool more = (t + 1 < T_);

        float decn0 = 0.f, decn1 = 0.f;
        if (more) { decn0 = hdecay[m0 + 1]; decn1 = hdecay[m1 + 1]; }

        // ---- phase A: stage pre-decayed h slice from source CTA w ----
        poll_ge(fh, (unsigned)t);
        {
            const float4* src = (const float4*)&g_h[p][grp][gr][w * 32 + gh * 4];
            float4 v0 = __ldcg(src + 0), v1 = __ldcg(src + 1);
            float4 v2 = __ldcg(src + 2), v3 = __ldcg(src + 3);
            float4* dst = (float4*)&asm_h[gr * 256 + w * 32 + gh * 4];
            dst[0] = v0; dst[1] = v1; dst[2] = v2; dst[3] = v3;
        }
        __syncwarp();

        // ---- phase B: merged z+r GEMM over own k-slice ----
        #pragma unroll 1
        for (int b = 0; b < NB; ++b) {
            unsigned long long az0 = 0, az1 = 0, ar0 = 0, ar1 = 0;
            const float* hrow = &asm_h[b * 256 + w * 32];
            #pragma unroll
            for (int q = 0; q < 8; ++q) {
                ulonglong2 hv = *(const ulonglong2*)(hrow + q * 4);
                fma2(az0, hv.x, uz2[2 * q]);
                fma2(az1, hv.y, uz2[2 * q + 1]);
                fma2(ar0, hv.x, ur2[2 * q]);
                fma2(ar1, hv.y, ur2[2 * q + 1]);
            }
            red_z[(w * 16 + b) * 32 + l] = add2(az0, az1);
            red_r[(w * 16 + b) * 32 + l] = add2(ar0, ar1);
        }
        __syncthreads();   // S1: partials + all h staging visible CTA-wide

        // ---- phase C: r reduce + publish rh slice ----
        float hd0, hd1;
        {
            unsigned long long s0 = 0, s1 = 0;
            #pragma unroll
            for (int ww = 0; ww < 8; ++ww) {
                s0 = add2(s0, red_r[(ww * 16 + w) * 32 + l]);
                s1 = add2(s1, red_r[(ww * 16 + w + 8) * 32 + l]);
            }
            float r0 = sigmoid_(fold2(s0) + xr0);
            float r1 = sigmoid_(fold2(s1) + xr1);
            hd0 = asm_h[w * 256 + j];
            hd1 = asm_h[(w + 8) * 256 + j];
            __stcg(&g_rh[p][grp][w][j],     r0 * hd0);
            __stcg(&g_rh[p][grp][w + 8][j], r1 * hd1);
        }
        __syncthreads();   // S2: all rh stores issued before release
        if (tid == 0) set_flag(myfrh, (unsigned)(t + 1));

        // ---- phase D: z reduce (local; fills producer skew) ----
        float zv0, zv1;
        {
            unsigned long long s0 = 0, s1 = 0;
            #pragma unroll
            for (int ww = 0; ww < 8; ++ww) {
                s0 = add2(s0, red_z[(ww * 16 + w) * 32 + l]);
                s1 = add2(s1, red_z[(ww * 16 + w + 8) * 32 + l]);
            }
            zv0 = sigmoid_(fold2(s0) + xz0);
            zv1 = sigmoid_(fold2(s1) + xz1);
        }

        // ---- phase E: stage rh slice from source CTA w ----
        poll_ge(frh, (unsigned)(t + 1));
        {
            const float4* src = (const float4*)&g_rh[p][grp][gr][w * 32 + gh * 4];
            float4 v0 = __ldcg(src + 0), v1 = __ldcg(src + 1);
            float4 v2 = __ldcg(src + 2), v3 = __ldcg(src + 3);
            float4* dst = (float4*)&asm_rh[gr * 256 + w * 32 + gh * 4];
            dst[0] = v0; dst[1] = v1; dst[2] = v2; dst[3] = v3;
        }
        __syncwarp();

        // ---- phase F: h GEMM (partials into red_r, safe after S2) ----
        #pragma unroll 1
        for (int b = 0; b < NB; ++b) {
            unsigned long long ah0 = 0, ah1 = 0;
            const float* hrow = &asm_rh[b * 256 + w * 32];
            #pragma unroll
            for (int q = 0; q < 8; ++q) {
                ulonglong2 hv = *(const ulonglong2*)(hrow + q * 4);
                fma2(ah0, hv.x, uh2[2 * q]);
                fma2(ah1, hv.y, uh2[2 * q + 1]);
            }
            red_r[(w * 16 + b) * 32 + l] = add2(ah0, ah1);
        }
        __syncthreads();   // S3

        // ---- phase G: h reduce, combine, publish pre-decayed h ----
        float h0, h1;
        {
            unsigned long long s0 = 0, s1 = 0;
            #pragma unroll
            for (int ww = 0; ww < 8; ++ww) {
                s0 = add2(s0, red_r[(ww * 16 + w) * 32 + l]);
                s1 = add2(s1, red_r[(ww * 16 + w + 8) * 32 + l]);
            }
            float hp0 = tanh_(fold2(s0) + xh0);
            float hp1 = tanh_(fold2(s1) + xh1);
            h0 = (1.f - zv0) * hd0 + zv0 * hp0;
            h1 = (1.f - zv1) * hd1 + zv1 * hp1;
            if (more) {
                __stcg(&g_h[(t + 1) & 1][grp][w][j],     h0 * decn0);
                __stcg(&g_h[(t + 1) & 1][grp][w + 8][j], h1 * decn1);
            }
        }
        __syncthreads();   // S4: all h stores issued before release
        if (more && tid == 0) set_flag(myfh, (unsigned)(t + 1));

        // ---- off critical path: outputs + next-step x prefetch ----
        out[m0 * 256 + j] = h0;
        out[m1 * 256 + j] = h1;
        if (more) {
            xz0 = g_xp[(m0 + 1) * 256 + j];          xz1 = g_xp[(m1 + 1) * 256 + j];
            xr0 = g_xp[MH + (m0 + 1) * 256 + j];     xr1 = g_xp[MH + (m1 + 1) * 256 + j];
            xh0 = g_xp[2 * MH + (m0 + 1) * 256 + j]; xh1 = g_xp[2 * MH + (m1 + 1) * 256 + j];
        }
    }
}

// ================= launch =================
extern "C" void kernel_launch(void* const* d_in, const int* /*in_sizes*/, int /*n_in*/,
                              void* d_out, int /*out_size*/)
{
    const float* x      = (const float*)d_in[0];
    const float* hdecay = (const float*)d_in[1];
    const float* Wr = (const float*)d_in[2];
    const float* Wz = (const float*)d_in[3];
    const float* Wh = (const float*)d_in[4];
    const float* Ur = (const float*)d_in[5];
    const float* Uz = (const float*)d_in[6];
    const float* Uh = (const float*)d_in[7];
    const float* br = (const float*)d_in[8];
    const float* bz = (const float*)d_in[9];
    const float* bh = (const float*)d_in[10];
    float* out = (float*)d_out;

    constexpr int SMEM_SCAN = 24576 * 4;   // 96KB dynamic
    cudaFuncSetAttribute(scan_kernel, cudaFuncAttributeMaxDynamicSharedMemorySize, SMEM_SCAN);

    proj_kernel<<<dim3(MTOT / 128, H_ / 64, 3), 256>>>(x, Wz, Wr, Wh, bz, br, bh);
    reset_kernel<<<256, 256>>>();
    scan_kernel<<<NBG * NC, 256, SMEM_SCAN>>>(Uz, Ur, Uh, hdecay, out);
}